// round 8
// baseline (speedup 1.0000x reference)
#include <cuda_runtime.h>
#include <cuda_fp16.h>
#include <math.h>

constexpr int FIN     = 8;
constexpr int E_TOTAL = 262144;
constexpr int NBASIS  = 10;
constexpr int HID     = 64;
constexpr int WN      = 384;
constexpr int NNODES  = 32768;

// Radial table: 16 live difference-functions of r on [0,3], fp16, 32B rows.
// Row p: h[0..7] = c0[u] = g_{u,2}-g_{u,1}; h[8..15] = c1[u] = g_{u,0}-g_{u,2}.
// curl0 = x.c0, curl1 = x.c1, curl2 = -(curl0+curl1).
constexpr int NB = 2048;
__device__ __half g_tab_h[(NB + 1) * 16];
__device__ float4 g_pos4[NNODES];     // padded positions
__device__ uint4  g_nf16[NNODES];     // node features as half8

// Bit-cast helpers (no __half2_as_uint intrinsic exists)
__device__ __forceinline__ unsigned h2_bits(__half2 h) {
    union { __half2 h; unsigned u; } c; c.h = h; return c.u;
}
__device__ __forceinline__ float2 h2f(unsigned u) {
    union { unsigned u; __half2 h; } c; c.u = u;
    return __half22float2(c.h);
}

// ---------------------------------------------------------------------------
// Setup kernel. Roles:
//   [0, T)            table build, 4 lanes per point (k-chunks of 16)
//   [T, T+Z)          zero the poisoned output
//   [T+Z, T+Z+P)      pos -> float4
//   [T+Z+P, ...)      nf -> half8
// ---------------------------------------------------------------------------
constexpr int STD       = 256;
constexpr int T_BLOCKS  = 33;    // 33*256 = 8448 >= 2049 points * 4 lanes
constexpr int Z_BLOCKS  = 96;    // 96*256 float4 = 98304 floats = out
constexpr int P4_BLOCKS = 128;   // 32768 nodes
constexpr int NF_BLOCKS = 128;   // 32768 nodes
constexpr int S_GRID    = T_BLOCKS + Z_BLOCKS + P4_BLOCKS + NF_BLOCKS;

__global__ void __launch_bounds__(STD)
setup_kernel(const float* __restrict__ nf,
             const float* __restrict__ pos,
             const float* __restrict__ W1,
             const float* __restrict__ W2,
             float* __restrict__ out) {
    const int bid = blockIdx.x;
    const int tid = threadIdx.x;

    if (bid < T_BLOCKS) {
        __shared__ float sW1[NBASIS * HID];   // 640
        __shared__ float sW2d[HID * 16];      // pre-differenced live W2 cols

        for (int i = tid; i < NBASIS * HID; i += STD) sW1[i] = W1[i];
        for (int i = tid; i < HID * 16; i += STD) {
            int k = i >> 4, c = i & 15, u = c & 7;
            const float* w = W2 + k * WN + u * 32;
            sW2d[i] = (c < 8) ? (w[2] - w[1]) : (w[0] - w[2]);
        }
        __syncthreads();

        int g  = bid * STD + tid;
        int p  = g >> 2;                      // table point
        int k0 = (g & 3) * 16;                // this lane's k-chunk

        float r = 3.0f * (float)min(p, NB) / (float)NB;

        float emb[NBASIS];
        const float inv_step = 11.0f / 3.0f;
        const float cA = 1.14136f * __expf(2.0f) * sqrtf(10.0f);
        #pragma unroll
        for (int j = 0; j < NBASIS; j++) {
            float v  = 3.0f * (float)(j + 1) / 11.0f;
            float dd = (r - v) * inv_step;
            float e  = 0.0f;
            if (fabsf(dd) < 1.0f) {
                float y = fmaxf(1.0f - dd * dd, 1e-7f);
                e = cA * __expf(-1.0f / y);
            }
            emb[j] = e;
        }

        float acc[16];
        #pragma unroll
        for (int c = 0; c < 16; c++) acc[c] = 0.0f;

        #pragma unroll
        for (int kk = 0; kk < 16; kk++) {
            float s = 0.0f;
            #pragma unroll
            for (int j = 0; j < NBASIS; j++)
                s = fmaf(emb[j], sW1[j * HID + k0 + kk], s);
            s *= 0.31622776601683794f;                    // 1/sqrt(10)
            float hk = __fdividef(s, 1.0f + __expf(-s));  // silu
            #pragma unroll
            for (int c = 0; c < 16; c++)
                acc[c] = fmaf(hk, sW2d[(k0 + kk) * 16 + c], acc[c]);
        }

        // Combine the 4 k-chunk lanes of this point (lanes g, g^1, g^2, g^3).
        #pragma unroll
        for (int o = 1; o <= 2; o <<= 1) {
            #pragma unroll
            for (int c = 0; c < 16; c++)
                acc[c] += __shfl_xor_sync(0xffffffffu, acc[c], o);
        }

        if ((g & 3) == 0 && p <= NB) {
            float t    = 10.0f * (1.0f - r * (1.0f / 3.0f));
            float wcut = (t > 0.0f) ? __expf(-1.0f / t) : 0.0f;
            float sc   = wcut * 0.04419417382415922f;   // (1/8)*(1/sqrt8)
            __half2* row = (__half2*)(g_tab_h + (size_t)p * 16);
            #pragma unroll
            for (int c = 0; c < 8; c++)
                row[c] = __floats2half2_rn(acc[2*c] * sc, acc[2*c+1] * sc);
        }
    } else if (bid < T_BLOCKS + Z_BLOCKS) {
        int i = (bid - T_BLOCKS) * STD + tid;         // zero poisoned output
        ((float4*)out)[i] = make_float4(0.f, 0.f, 0.f, 0.f);
    } else if (bid < T_BLOCKS + Z_BLOCKS + P4_BLOCKS) {
        int n = (bid - T_BLOCKS - Z_BLOCKS) * STD + tid;
        g_pos4[n] = make_float4(__ldg(pos + 3*n), __ldg(pos + 3*n + 1),
                                __ldg(pos + 3*n + 2), 0.f);
    } else {
        int n = (bid - T_BLOCKS - Z_BLOCKS - P4_BLOCKS) * STD + tid;
        const float4* xp = (const float4*)(nf + (size_t)n * FIN);
        float4 a = __ldg(xp), b = __ldg(xp + 1);
        uint4 h;
        h.x = h2_bits(__floats2half2_rn(a.x, a.y));
        h.y = h2_bits(__floats2half2_rn(a.z, a.w));
        h.z = h2_bits(__floats2half2_rn(b.x, b.y));
        h.w = h2_bits(__floats2half2_rn(b.z, b.w));
        g_nf16[n] = h;
    }
}

// ---------------------------------------------------------------------------
// Edge kernel: 2 edges/thread, front-batched loads for latency hiding.
// ---------------------------------------------------------------------------
__device__ __forceinline__ float dot8(uint4 t, float2 X0, float2 X1,
                                      float2 X2, float2 X3) {
    float2 t0 = h2f(t.x), t1 = h2f(t.y), t2 = h2f(t.z), t3 = h2f(t.w);
    return X0.x*t0.x + X0.y*t0.y + X1.x*t1.x + X1.y*t1.y
         + X2.x*t2.x + X2.y*t2.y + X3.x*t3.x + X3.y*t3.y;
}

__global__ void __launch_bounds__(256)
edge_kernel(const int* __restrict__ esrc,
            const int* __restrict__ edst,
            float*     __restrict__ out) {
    const int base = blockIdx.x * 512 + threadIdx.x;
    const int e0 = base, e1 = base + 256;

    // ---- batch 1: indices (coalesced) ----
    int s0 = __ldg(esrc + e0), d0 = __ldg(edst + e0);
    int s1 = __ldg(esrc + e1), d1 = __ldg(edst + e1);

    // ---- batch 2: random gathers ----
    float4 ps0 = __ldg(g_pos4 + s0), pd0 = __ldg(g_pos4 + d0);
    float4 ps1 = __ldg(g_pos4 + s1), pd1 = __ldg(g_pos4 + d1);
    uint4  xa  = __ldg(g_nf16 + s0);
    uint4  xb  = __ldg(g_nf16 + s1);

    float ex0 = ps0.x-pd0.x, ey0 = ps0.y-pd0.y, ez0 = ps0.z-pd0.z;
    float ex1 = ps1.x-pd1.x, ey1 = ps1.y-pd1.y, ez1 = ps1.z-pd1.z;
    float r0 = sqrtf(fmaf(ex0,ex0, fmaf(ey0,ey0, fmaf(ez0,ez0, 1e-18f))));
    float r1 = sqrtf(fmaf(ex1,ex1, fmaf(ey1,ey1, fmaf(ez1,ez1, 1e-18f))));
    bool l0 = (r0 < 3.0f), l1 = (r1 < 3.0f);

    float f0 = r0 * ((float)NB / 3.0f);
    float f1 = r1 * ((float)NB / 3.0f);
    int i0 = min((int)f0, NB - 1);
    int i1 = min((int)f1, NB - 1);
    float fr0 = f0 - floorf(f0);
    float fr1 = f1 - floorf(f1);

    // ---- batch 3: table rows (always load, clamped index) ----
    const uint4* tp0 = (const uint4*)(g_tab_h + (size_t)i0 * 16);
    const uint4* tp1 = (const uint4*)(g_tab_h + (size_t)i1 * 16);
    uint4 ta0 = __ldg(tp0 + 0), tb0 = __ldg(tp0 + 1);
    uint4 tc0 = __ldg(tp0 + 2), td0 = __ldg(tp0 + 3);
    uint4 ta1 = __ldg(tp1 + 0), tb1 = __ldg(tp1 + 1);
    uint4 tc1 = __ldg(tp1 + 2), td1 = __ldg(tp1 + 3);

    // ---- compute edge 0 ----
    {
        float2 X0 = h2f(xa.x), X1 = h2f(xa.y), X2 = h2f(xa.z), X3 = h2f(xa.w);
        float c0a = dot8(ta0, X0, X1, X2, X3);
        float c1a = dot8(tb0, X0, X1, X2, X3);
        float c0b = dot8(tc0, X0, X1, X2, X3);
        float c1b = dot8(td0, X0, X1, X2, X3);
        float curl0 = fmaf(fr0, c0b - c0a, c0a);
        float curl1 = fmaf(fr0, c1b - c1a, c1a);
        if (l0) {
            atomicAdd(out + 3*d0 + 0, curl0);
            atomicAdd(out + 3*d0 + 1, curl1);
            atomicAdd(out + 3*d0 + 2, -(curl0 + curl1));
        }
    }
    // ---- compute edge 1 ----
    {
        float2 X0 = h2f(xb.x), X1 = h2f(xb.y), X2 = h2f(xb.z), X3 = h2f(xb.w);
        float c0a = dot8(ta1, X0, X1, X2, X3);
        float c1a = dot8(tb1, X0, X1, X2, X3);
        float c0b = dot8(tc1, X0, X1, X2, X3);
        float c1b = dot8(td1, X0, X1, X2, X3);
        float curl0 = fmaf(fr1, c0b - c0a, c0a);
        float curl1 = fmaf(fr1, c1b - c1a, c1a);
        if (l1) {
            atomicAdd(out + 3*d1 + 0, curl0);
            atomicAdd(out + 3*d1 + 1, curl1);
            atomicAdd(out + 3*d1 + 2, -(curl0 + curl1));
        }
    }
}

// ---------------------------------------------------------------------------
extern "C" void kernel_launch(void* const* d_in, const int* in_sizes, int n_in,
                              void* d_out, int out_size) {
    const float* nf   = (const float*)d_in[0];
    const float* pos  = (const float*)d_in[1];
    const int*   esrc = (const int*)  d_in[2];
    const int*   edst = (const int*)  d_in[3];
    const float* W1   = (const float*)d_in[4];
    const float* W2   = (const float*)d_in[5];
    float* out = (float*)d_out;

    setup_kernel<<<S_GRID, STD>>>(nf, pos, W1, W2, out);
    edge_kernel<<<E_TOTAL / 512, 256>>>(esrc, edst, out);
}

// round 9
// speedup vs baseline: 1.0137x; 1.0137x over previous
#include <cuda_runtime.h>
#include <cuda_fp16.h>
#include <math.h>

constexpr int FIN     = 8;
constexpr int E_TOTAL = 262144;
constexpr int NBASIS  = 10;
constexpr int HID     = 64;
constexpr int WN      = 384;
constexpr int NNODES  = 32768;

// Radial table: 16 live difference-functions of r on [0,3], fp16, 32B rows.
// Row p: h[0..7] = c0[u] = g_{u,2}-g_{u,1}; h[8..15] = c1[u] = g_{u,0}-g_{u,2}.
// curl0 = x.c0, curl1 = x.c1, curl2 = -(curl0+curl1).
constexpr int NB = 2048;
__device__ __half g_tab_h[(NB + 1) * 16];
__device__ float4 g_pos4[NNODES];     // padded positions
__device__ uint4  g_nf16[NNODES];     // node features as half8

__device__ __forceinline__ unsigned h2_bits(__half2 h) {
    union { __half2 h; unsigned u; } c; c.h = h; return c.u;
}
__device__ __forceinline__ float2 h2f(unsigned u) {
    union { unsigned u; __half2 h; } c; c.u = u;
    return __half22float2(c.h);
}

// ---------------------------------------------------------------------------
// Setup kernel roles:  [0,T) table (4 lanes/point), [T,T+P) pos->float4,
// [T+P,...) nf->half8.  Output zeroing is a cudaMemsetAsync node.
// ---------------------------------------------------------------------------
constexpr int STD       = 256;
constexpr int T_BLOCKS  = 33;    // 33*256 = 8448 >= 2049 points * 4 lanes
constexpr int P4_BLOCKS = 128;   // 32768 nodes
constexpr int NF_BLOCKS = 128;   // 32768 nodes
constexpr int S_GRID    = T_BLOCKS + P4_BLOCKS + NF_BLOCKS;   // 289

__global__ void __launch_bounds__(STD)
setup_kernel(const float* __restrict__ nf,
             const float* __restrict__ pos,
             const float* __restrict__ W1,
             const float* __restrict__ W2) {
    const int bid = blockIdx.x;
    const int tid = threadIdx.x;

    if (bid < T_BLOCKS) {
        __shared__ float sW1[NBASIS * HID];   // 640
        __shared__ float sW2d[HID * 16];      // pre-differenced live W2 cols

        for (int i = tid; i < NBASIS * HID; i += STD) sW1[i] = W1[i];
        for (int i = tid; i < HID * 16; i += STD) {
            int k = i >> 4, c = i & 15, u = c & 7;
            const float* w = W2 + k * WN + u * 32;
            sW2d[i] = (c < 8) ? (w[2] - w[1]) : (w[0] - w[2]);
        }
        __syncthreads();

        int g  = bid * STD + tid;
        int p  = g >> 2;                      // table point
        int k0 = (g & 3) * 16;                // this lane's k-chunk

        float r = 3.0f * (float)min(p, NB) / (float)NB;

        float emb[NBASIS];
        const float inv_step = 11.0f / 3.0f;
        const float cA = 1.14136f * __expf(2.0f) * sqrtf(10.0f);
        #pragma unroll
        for (int j = 0; j < NBASIS; j++) {
            float v  = 3.0f * (float)(j + 1) / 11.0f;
            float dd = (r - v) * inv_step;
            float e  = 0.0f;
            if (fabsf(dd) < 1.0f) {
                float y = fmaxf(1.0f - dd * dd, 1e-7f);
                e = cA * __expf(-1.0f / y);
            }
            emb[j] = e;
        }

        float acc[16];
        #pragma unroll
        for (int c = 0; c < 16; c++) acc[c] = 0.0f;

        #pragma unroll
        for (int kk = 0; kk < 16; kk++) {
            float s = 0.0f;
            #pragma unroll
            for (int j = 0; j < NBASIS; j++)
                s = fmaf(emb[j], sW1[j * HID + k0 + kk], s);
            s *= 0.31622776601683794f;                    // 1/sqrt(10)
            float hk = __fdividef(s, 1.0f + __expf(-s));  // silu
            #pragma unroll
            for (int c = 0; c < 16; c++)
                acc[c] = fmaf(hk, sW2d[(k0 + kk) * 16 + c], acc[c]);
        }

        #pragma unroll
        for (int o = 1; o <= 2; o <<= 1) {
            #pragma unroll
            for (int c = 0; c < 16; c++)
                acc[c] += __shfl_xor_sync(0xffffffffu, acc[c], o);
        }

        if ((g & 3) == 0 && p <= NB) {
            float t    = 10.0f * (1.0f - r * (1.0f / 3.0f));
            float wcut = (t > 0.0f) ? __expf(-1.0f / t) : 0.0f;
            float sc   = wcut * 0.04419417382415922f;   // (1/8)*(1/sqrt8)
            __half2* row = (__half2*)(g_tab_h + (size_t)p * 16);
            #pragma unroll
            for (int c = 0; c < 8; c++)
                row[c] = __floats2half2_rn(acc[2*c] * sc, acc[2*c+1] * sc);
        }
    } else if (bid < T_BLOCKS + P4_BLOCKS) {
        int n = (bid - T_BLOCKS) * STD + tid;
        g_pos4[n] = make_float4(__ldg(pos + 3*n), __ldg(pos + 3*n + 1),
                                __ldg(pos + 3*n + 2), 0.f);
    } else {
        int n = (bid - T_BLOCKS - P4_BLOCKS) * STD + tid;
        const float4* xp = (const float4*)(nf + (size_t)n * FIN);
        float4 a = __ldg(xp), b = __ldg(xp + 1);
        uint4 h;
        h.x = h2_bits(__floats2half2_rn(a.x, a.y));
        h.y = h2_bits(__floats2half2_rn(a.z, a.w));
        h.z = h2_bits(__floats2half2_rn(b.x, b.y));
        h.w = h2_bits(__floats2half2_rn(b.z, b.w));
        g_nf16[n] = h;
    }
}

// ---------------------------------------------------------------------------
// Edge kernel: 1 edge/thread; fp16 table lerp; parity-split vector atomics.
// ---------------------------------------------------------------------------
__device__ __forceinline__ float dot8(uint4 t, float2 X0, float2 X1,
                                      float2 X2, float2 X3) {
    float2 t0 = h2f(t.x), t1 = h2f(t.y), t2 = h2f(t.z), t3 = h2f(t.w);
    return X0.x*t0.x + X0.y*t0.y + X1.x*t1.x + X1.y*t1.y
         + X2.x*t2.x + X2.y*t2.y + X3.x*t3.x + X3.y*t3.y;
}

__global__ void __launch_bounds__(256)
edge_kernel(const int* __restrict__ esrc,
            const int* __restrict__ edst,
            float*     __restrict__ out) {
    int e = blockIdx.x * 256 + threadIdx.x;

    int s = __ldg(esrc + e);
    int d = __ldg(edst + e);

    float4 ps = __ldg(g_pos4 + s);
    float4 pd = __ldg(g_pos4 + d);
    uint4  xh = __ldg(g_nf16 + s);

    float dx = ps.x - pd.x, dy = ps.y - pd.y, dz = ps.z - pd.z;
    float r  = sqrtf(fmaf(dx, dx, fmaf(dy, dy, fmaf(dz, dz, 1e-18f))));

    if (r >= 3.0f) return;                    // w_cut == 0

    float ff = r * ((float)NB / 3.0f);
    int   i  = (int)ff;
    float fr = ff - (float)i;

    const uint4* tp = (const uint4*)(g_tab_h + (size_t)i * 16);
    uint4 ta = __ldg(tp + 0);   // c0, row i
    uint4 tb = __ldg(tp + 1);   // c1, row i
    uint4 tc = __ldg(tp + 2);   // c0, row i+1
    uint4 td = __ldg(tp + 3);   // c1, row i+1

    float2 X0 = h2f(xh.x), X1 = h2f(xh.y), X2 = h2f(xh.z), X3 = h2f(xh.w);
    float c0a = dot8(ta, X0, X1, X2, X3);
    float c1a = dot8(tb, X0, X1, X2, X3);
    float c0b = dot8(tc, X0, X1, X2, X3);
    float c1b = dot8(td, X0, X1, X2, X3);

    float curl0 = fmaf(fr, c0b - c0a, c0a);
    float curl1 = fmaf(fr, c1b - c1a, c1a);
    float curl2 = -(curl0 + curl1);

    // 2 atomics instead of 3: out+3d is 8B-aligned iff d even; else out+3d+1.
    if (d & 1) {
        atomicAdd(out + 3*d, curl0);
        atomicAdd((float2*)(out + 3*d + 1), make_float2(curl1, curl2));
    } else {
        atomicAdd((float2*)(out + 3*d), make_float2(curl0, curl1));
        atomicAdd(out + 3*d + 2, curl2);
    }
}

// ---------------------------------------------------------------------------
extern "C" void kernel_launch(void* const* d_in, const int* in_sizes, int n_in,
                              void* d_out, int out_size) {
    const float* nf   = (const float*)d_in[0];
    const float* pos  = (const float*)d_in[1];
    const int*   esrc = (const int*)  d_in[2];
    const int*   edst = (const int*)  d_in[3];
    const float* W1   = (const float*)d_in[4];
    const float* W2   = (const float*)d_in[5];
    float* out = (float*)d_out;

    cudaMemsetAsync(out, 0, (size_t)out_size * sizeof(float), 0);
    setup_kernel<<<S_GRID, STD>>>(nf, pos, W1, W2);
    edge_kernel<<<E_TOTAL / 256, 256>>>(esrc, edst, out);
}